// round 3
// baseline (speedup 1.0000x reference)
#include <cuda_runtime.h>
#include <cstdint>

// Gegenbauer (alpha=0.5 -> Legendre) embedding: out[row, i-1] = C_i(x[row]), i=1..64.
// Round 3: recurrence -> register half-row buffer -> conflict-free rotated STS
// into LINEAR smem -> one cp.async.bulk (TMA S2G) 32KB store per block.

#define DIM_OUT 64
#define RPB 128              // rows per block == threads per block
#define TILE_BYTES (RPB * DIM_OUT * 4)   // 32768

__device__ __forceinline__ uint32_t smem_u32(const void* p) {
    uint32_t a;
    asm("{ .reg .u64 t; cvta.to.shared.u64 t, %1; cvt.u32.u64 %0, t; }"
        : "=r"(a) : "l"(p));
    return a;
}

__global__ void __launch_bounds__(RPB) geg_kernel(const float* __restrict__ x,
                                                  float* __restrict__ out,
                                                  int n) {
    __shared__ __align__(16) float s[RPB * DIM_OUT];   // 32 KB, linear = gmem layout

    const int tid = threadIdx.x;
    const size_t row = (size_t)blockIdx.x * RPB + tid;
    const bool full_tile = ((size_t)(blockIdx.x + 1) * RPB <= (size_t)n);

    const float xv = (row < (size_t)n) ? x[row] : 0.0f;

    float4* s4 = reinterpret_cast<float4*>(s);
    const int t8 = tid & 7;

    // Half-row register buffer: 8 float4 = 32 coefficients.
    float4 buf[8];
    float* bf = reinterpret_cast<float*>(buf);

    float prev2 = 1.0f;   // C_0
    float prev  = xv;     // C_1 (alpha=0.5)
    bf[0] = xv;           // c[0] = C_1

    // C_i = ((2i-1)*x*C_{i-1} + (1-i)*C_{i-2}) * (1/i)   (alpha = 0.5)
    #pragma unroll
    for (int i = 2; i <= DIM_OUT; ++i) {
        const float A = (float)(2 * i - 1);
        const float B = (float)(1 - i);
        const float r = 1.0f / (float)i;
        const float ci = (A * xv * prev + B * prev2) * r;
        const int k = i - 1;          // 0-based coefficient index
        bf[k & 31] = ci;              // compile-time slot (fully unrolled)
        prev2 = prev;
        prev  = ci;

        if ((k & 31) == 31) {
            // Flush group g (columns g*8 .. g*8+7 in float4 units) with rotated
            // column order: substep q -> column (q+t)&7. Each 8-lane phase hits
            // all 8 distinct 4-bank groups -> conflict-free STS.128 into linear smem.
            const int g = k >> 5;     // 0 or 1
            #pragma unroll
            for (int q = 0; q < 8; ++q) {
                const int c = (q + t8) & 7;
                s4[tid * (DIM_OUT / 4) + g * 8 + c] = buf[c];
            }
        }
    }

    __syncthreads();

    if (full_tile) {
        if (tid == 0) {
            asm volatile("fence.proxy.async.shared::cta;" ::: "memory");
            float* gdst = out + (size_t)blockIdx.x * (RPB * DIM_OUT);
            uint32_t ssrc = smem_u32(s);
            asm volatile(
                "cp.async.bulk.global.shared::cta.bulk_group [%0], [%1], %2;"
                :: "l"(gdst), "r"(ssrc), "n"(TILE_BYTES) : "memory");
            asm volatile("cp.async.bulk.commit_group;" ::: "memory");
            asm volatile("cp.async.bulk.wait_group 0;" ::: "memory");
        }
    } else {
        // Tail block (n not multiple of RPB): coalesced per-thread fallback.
        const size_t blk_base_f4 = (size_t)blockIdx.x * (RPB * DIM_OUT / 4);
        float4* __restrict__ o4 = reinterpret_cast<float4*>(out);
        const size_t total_f4 = ((size_t)n * DIM_OUT) / 4;
        #pragma unroll
        for (int it = 0; it < DIM_OUT / 4; ++it) {
            const size_t f = (size_t)it * RPB + tid;
            const size_t g = blk_base_f4 + f;
            if (g < total_f4) o4[g] = s4[f];
        }
    }
}

extern "C" void kernel_launch(void* const* d_in, const int* in_sizes, int n_in,
                              void* d_out, int out_size) {
    const float* x = (const float*)d_in[0];
    float* out = (float*)d_out;
    int n = in_sizes[0];   // 2,000,000 rows
    int blocks = (n + RPB - 1) / RPB;
    geg_kernel<<<blocks, RPB>>>(x, out, n);
}

// round 4
// speedup vs baseline: 3.0769x; 3.0769x over previous
#include <cuda_runtime.h>

// Gegenbauer (alpha=0.5 -> Legendre) embedding: out[row, i-1] = C_i(x[row]), i=1..64.
// Round 4: two-pass staging (32 columns at a time) halves smem per CTA
// -> ~2x occupancy, and pass-B compute overlaps pass-A stores.
// Each row-chunk is 128B, so copy-out warps still write full 128B lines.

#define DIM_OUT 64
#define RPB 128          // rows per block == threads
#define HF4 8            // float4 per half-row (32 floats = 128B)
#define PAD 9            // smem row stride in float4: conflict-free phases

__global__ void __launch_bounds__(RPB) geg_kernel(const float* __restrict__ x,
                                                  float* __restrict__ out,
                                                  int n) {
    __shared__ float4 s[RPB * PAD];   // 18,432 B

    const int tid = threadIdx.x;
    const size_t row = (size_t)blockIdx.x * RPB + tid;
    const float xv = (row < (size_t)n) ? x[row] : 0.0f;

    float4* __restrict__ o4 = reinterpret_cast<float4*>(out);
    const size_t base_f4 = (size_t)blockIdx.x * RPB * (DIM_OUT / 4);
    const size_t total_f4 = ((size_t)n * DIM_OUT) / 4;

    float c[32];
    float prev2 = 1.0f;   // C_0
    float prev  = xv;     // C_1 (alpha = 0.5)
    c[0] = xv;

    // ---- Pass A: C_1..C_32 ----
    // C_i = ((2i-1)*x*C_{i-1} + (1-i)*C_{i-2}) * (1/i)
    #pragma unroll
    for (int i = 2; i <= 32; ++i) {
        const float A = (float)(2 * i - 1);
        const float B = (float)(1 - i);
        const float r = 1.0f / (float)i;
        const float ci = (A * xv * prev + B * prev2) * r;
        c[i - 1] = ci;
        prev2 = prev;
        prev  = ci;
    }

    #pragma unroll
    for (int j = 0; j < HF4; ++j)
        s[tid * PAD + j] = make_float4(c[4*j], c[4*j+1], c[4*j+2], c[4*j+3]);
    __syncthreads();

    // Coalesced copy-out of column block 0 (cols 0..31 of each row).
    #pragma unroll
    for (int j = 0; j < HF4; ++j) {
        const int f = j * RPB + tid;       // index within 128x8 f4 tile
        const int r = f >> 3;              // row within block
        const int cq = f & 7;              // f4 column within half-row
        const size_t g = base_f4 + (size_t)r * (DIM_OUT / 4) + cq;
        if (g < total_f4) o4[g] = s[r * PAD + cq];
    }
    __syncthreads();

    // ---- Pass B: C_33..C_64 (overlaps pass-A stores in flight) ----
    #pragma unroll
    for (int i = 33; i <= DIM_OUT; ++i) {
        const float A = (float)(2 * i - 1);
        const float B = (float)(1 - i);
        const float r = 1.0f / (float)i;
        const float ci = (A * xv * prev + B * prev2) * r;
        c[i - 33] = ci;
        prev2 = prev;
        prev  = ci;
    }

    #pragma unroll
    for (int j = 0; j < HF4; ++j)
        s[tid * PAD + j] = make_float4(c[4*j], c[4*j+1], c[4*j+2], c[4*j+3]);
    __syncthreads();

    // Coalesced copy-out of column block 1 (cols 32..63 of each row).
    #pragma unroll
    for (int j = 0; j < HF4; ++j) {
        const int f = j * RPB + tid;
        const int r = f >> 3;
        const int cq = f & 7;
        const size_t g = base_f4 + (size_t)r * (DIM_OUT / 4) + HF4 + cq;
        if (g < total_f4) o4[g] = s[r * PAD + cq];
    }
}

extern "C" void kernel_launch(void* const* d_in, const int* in_sizes, int n_in,
                              void* d_out, int out_size) {
    const float* x = (const float*)d_in[0];
    float* out = (float*)d_out;
    int n = in_sizes[0];   // 2,000,000 rows
    int blocks = (n + RPB - 1) / RPB;
    geg_kernel<<<blocks, RPB>>>(x, out, n);
}